// round 3
// baseline (speedup 1.0000x reference)
#include <cuda_runtime.h>
#include <math.h>

// ---------------- Problem constants ----------------
#define S_LEN 2048
#define BATCH 64
#define FEAT  40
#define EMBD  128
#define HID   256

// Partition: 4 batch-groups x 32 hidden-slices = 128 persistent blocks
#define NBG  4
#define NSL  32
#define NBLK 128
#define TPB  256

// Virtual K dims
#define K0  296          // 40 (x) + 256 (h0 prev)
#define K0P 304          // padded row stride (floats)
#define K0F 74           // K0/4 float4s
#define K1  512          // 256 (h0) + 256 (h1 prev)
#define K1P 520
#define K1F 128

// SMEM layout (float offsets)
#define OFF_W0   0
#define OFF_W1   (OFF_W0 + 32*K0P)        // 9728
#define OFF_IN0  (OFF_W1 + 32*K1P)        // 26368
#define OFF_IN1  (OFF_IN0 + 16*K0P)       // 31232
#define OFF_RED0 (OFF_IN1 + 16*K1P)       // 39552
#define OFF_RED1 (OFF_RED0 + 32*16*6)     // 42624
#define OFF_GATE (OFF_RED1 + 32*16*10)    // 47744
#define OFF_BIAS (OFF_GATE + 1024)        // 48768
#define OFF_WOUT (OFF_BIAS + 64)          // 48832
#define SMEM_FLOATS (OFF_WOUT + 8)        // 48840
#define SMEM_BYTES  (SMEM_FLOATS * 4)     // 195360

// ---------------- Device scratch (static, no runtime alloc) ----------------
__device__ float    g_Wfold[1024 * FEAT];          // W_ih0 @ W_in  [1024,40]
__device__ float    g_bias0[1024];                 // W_ih0@b_in + b_ih0 + b_hh0
__device__ float    g_bias1[1024];                 // b_ih1 + b_hh1
__device__ float    g_h0buf[2][BATCH * HID];       // double-buffered h0 (by time parity)
__device__ float    g_h1buf[2][BATCH * HID];       // double-buffered h1 (by time parity)
__device__ unsigned g_ctr[NBG];                    // per batch-group arrival counters
__device__ float    g_pdot[(size_t)S_LEN * BATCH * NSL];  // partial output dots

// ---------------- Prologue: fold input projection into layer0 ----------------
__global__ void fold_kernel(const float* __restrict__ W_ih0,
                            const float* __restrict__ W_in,
                            const float* __restrict__ b_in,
                            const float* __restrict__ b_ih0,
                            const float* __restrict__ b_hh0,
                            const float* __restrict__ b_ih1,
                            const float* __restrict__ b_hh1)
{
    int r = blockIdx.x;          // 0..1023 gate row
    int t = threadIdx.x;         // 0..63
    if (t < FEAT) {
        float s = 0.f;
        for (int e = 0; e < EMBD; e++)
            s += W_ih0[r * EMBD + e] * W_in[e * FEAT + t];
        g_Wfold[r * FEAT + t] = s;
    } else if (t == 63) {
        float s = b_ih0[r] + b_hh0[r];
        for (int e = 0; e < EMBD; e++)
            s += W_ih0[r * EMBD + e] * b_in[e];
        g_bias0[r] = s;
        g_bias1[r] = b_ih1[r] + b_hh1[r];
    }
}

// ---------------- Prologue: zero state buffers + barrier counters ----------------
__global__ void init_kernel()
{
    int i = blockIdx.x * blockDim.x + threadIdx.x;   // 0..32767
    ((float*)g_h0buf)[i] = 0.f;
    ((float*)g_h1buf)[i] = 0.f;
    if (i < NBG) g_ctr[i] = 0u;
}

// ---------------- Persistent wavefront recurrence kernel ----------------
__global__ void __launch_bounds__(TPB, 1)
lstm_persist(const float* __restrict__ in_states,
             const float* __restrict__ W_hh0,
             const float* __restrict__ W_ih1,
             const float* __restrict__ W_hh1,
             const float* __restrict__ W_out)
{
    extern __shared__ float sm[];
    const int tid   = threadIdx.x;
    const int slice = blockIdx.x & 31;   // hidden slice: owns hidden units slice*8 .. slice*8+7
    const int bg    = blockIdx.x >> 5;   // batch group: batches bg*16 .. bg*16+15

    // ---- Load weights into SMEM (concatenated K layouts) ----
    // Wcat0[r][k] : k<40 -> Wfold ; k>=40 -> W_hh0[., k-40]   (rows r = gate*8 + u)
    for (int i = tid; i < 32 * K0; i += TPB) {
        int r = i / K0, k = i - r * K0;
        int gate = r >> 3, u = r & 7;
        int grow = gate * 256 + slice * 8 + u;
        float v = (k < FEAT) ? g_Wfold[grow * FEAT + k]
                             : W_hh0[grow * HID + (k - FEAT)];
        sm[OFF_W0 + r * K0P + k] = v;
    }
    // Wcat1[r][k] : k<256 -> W_ih1 ; k>=256 -> W_hh1
    for (int i = tid; i < 32 * K1; i += TPB) {
        int r = i >> 9, k = i & 511;
        int gate = r >> 3, u = r & 7;
        int grow = gate * 256 + slice * 8 + u;
        float v = (k < HID) ? W_ih1[grow * HID + k]
                            : W_hh1[grow * HID + (k - HID)];
        sm[OFF_W1 + r * K1P + k] = v;
    }
    if (tid < 32) {
        int gate = tid >> 3, u = tid & 7;
        int grow = gate * 256 + slice * 8 + u;
        sm[OFF_BIAS + tid]      = g_bias0[grow];
        sm[OFF_BIAS + 32 + tid] = g_bias1[grow];
    }
    if (tid < 8) sm[OFF_WOUT + tid] = W_out[slice * 8 + tid];

    // Update-phase role of this thread: one (layer, batch, unit) cell state
    const int up_layer = tid >> 7;
    const int up_b     = (tid >> 3) & 15;
    const int up_u     = tid & 7;
    float cst = 0.f;

    __syncthreads();

    // ---- Wavefront: step s computes h0[s] (layer0) and h1[s-1] (layer1) ----
    for (int s = 0; s <= S_LEN; s++) {

        // ---- Stage inputs into SMEM ----
        if (s < S_LEN) {
            for (int i = tid; i < 16 * FEAT; i += TPB) {
                int b = i / FEAT, f = i - b * FEAT;
                sm[OFF_IN0 + b * K0P + f] =
                    in_states[((size_t)(bg * 16 + b) * S_LEN + s) * FEAT + f];
            }
        }
        {
            // h0[s-1] lives in g_h0buf[(s-1)&1] ; h1[s-2] lives in g_h1buf[(s-2)&1]=g_h1buf[s&1]
            const float4* h0p = (const float4*)(g_h0buf[(s + 1) & 1] + bg * 16 * HID);
            const float4* h1p = (const float4*)(g_h1buf[s & 1]       + bg * 16 * HID);
            for (int i = tid; i < 16 * 64; i += TPB) {   // 1024 float4s
                int b = i >> 6, k4 = i & 63;
                float4 v = h0p[b * 64 + k4];
                *(float4*)&sm[OFF_IN0 + b * K0P + FEAT + k4 * 4] = v;
                *(float4*)&sm[OFF_IN1 + b * K1P + k4 * 4]        = v;
                float4 w = h1p[b * 64 + k4];
                *(float4*)&sm[OFF_IN1 + b * K1P + HID + k4 * 4]  = w;
            }
        }
        __syncthreads();

        // ---- GEMM phase: 3 warps layer0 (K=296, 6-way ksplit),
        //                  5 warps layer1 (K=512, 10-way ksplit) ----
        if (tid < 96) {
            if (s < S_LEN) {
                int tile = tid & 15, ks = tid >> 4;       // ks 0..5
                int rg = tile >> 1, bh = tile & 1;
                const float* Wp = sm + OFF_W0 + (rg * 4) * K0P;
                const float* Ip = sm + OFF_IN0 + (bh * 8) * K0P;
                int kb = ks * 13;
                int ke = kb + 13; if (ke > K0F) ke = K0F;
                float acc[4][8];
                #pragma unroll
                for (int r = 0; r < 4; r++)
                    #pragma unroll
                    for (int b = 0; b < 8; b++) acc[r][b] = 0.f;
                for (int kf = kb; kf < ke; kf++) {
                    float4 w0 = *(const float4*)(Wp + kf * 4);
                    float4 w1 = *(const float4*)(Wp + K0P + kf * 4);
                    float4 w2 = *(const float4*)(Wp + 2 * K0P + kf * 4);
                    float4 w3 = *(const float4*)(Wp + 3 * K0P + kf * 4);
                    #pragma unroll
                    for (int b = 0; b < 8; b++) {
                        float4 h = *(const float4*)(Ip + b * K0P + kf * 4);
                        acc[0][b] += w0.x * h.x; acc[0][b] += w0.y * h.y;
                        acc[0][b] += w0.z * h.z; acc[0][b] += w0.w * h.w;
                        acc[1][b] += w1.x * h.x; acc[1][b] += w1.y * h.y;
                        acc[1][b] += w1.z * h.z; acc[1][b] += w1.w * h.w;
                        acc[2][b] += w2.x * h.x; acc[2][b] += w2.y * h.y;
                        acc[2][b] += w2.z * h.z; acc[2][b] += w2.w * h.w;
                        acc[3][b] += w3.x * h.x; acc[3][b] += w3.y * h.y;
                        acc[3][b] += w3.z * h.z; acc[3][b] += w3.w * h.w;
                    }
                }
                #pragma unroll
                for (int r = 0; r < 4; r++)
                    #pragma unroll
                    for (int b = 0; b < 8; b++)
                        sm[OFF_RED0 + ((rg * 4 + r) * 16 + bh * 8 + b) * 6 + ks] = acc[r][b];
            }
        } else {
            if (s >= 1) {
                int t2 = tid - 96;
                int tile = t2 & 15, ks = t2 >> 4;         // ks 0..9
                int rg = tile >> 1, bh = tile & 1;
                const float* Wp = sm + OFF_W1 + (rg * 4) * K1P;
                const float* Ip = sm + OFF_IN1 + (bh * 8) * K1P;
                int kb = ks * 13;
                int ke = kb + 13; if (ke > K1F) ke = K1F;
                float acc[4][8];
                #pragma unroll
                for (int r = 0; r < 4; r++)
                    #pragma unroll
                    for (int b = 0; b < 8; b++) acc[r][b] = 0.f;
                for (int kf = kb; kf < ke; kf++) {
                    float4 w0 = *(const float4*)(Wp + kf * 4);
                    float4 w1 = *(const float4*)(Wp + K1P + kf * 4);
                    float4 w2 = *(const float4*)(Wp + 2 * K1P + kf * 4);
                    float4 w3 = *(const float4*)(Wp + 3 * K1P + kf * 4);
                    #pragma unroll
                    for (int b = 0; b < 8; b++) {
                        float4 h = *(const float4*)(Ip + b * K1P + kf * 4);
                        acc[0][b] += w0.x * h.x; acc[0][b] += w0.y * h.y;
                        acc[0][b] += w0.z * h.z; acc[0][b] += w0.w * h.w;
                        acc[1][b] += w1.x * h.x; acc[1][b] += w1.y * h.y;
                        acc[1][b] += w1.z * h.z; acc[1][b] += w1.w * h.w;
                        acc[2][b] += w2.x * h.x; acc[2][b] += w2.y * h.y;
                        acc[2][b] += w2.z * h.z; acc[2][b] += w2.w * h.w;
                        acc[3][b] += w3.x * h.x; acc[3][b] += w3.y * h.y;
                        acc[3][b] += w3.z * h.z; acc[3][b] += w3.w * h.w;
                    }
                }
                #pragma unroll
                for (int r = 0; r < 4; r++)
                    #pragma unroll
                    for (int b = 0; b < 8; b++)
                        sm[OFF_RED1 + ((rg * 4 + r) * 16 + bh * 8 + b) * 10 + ks] = acc[r][b];
            }
        }
        __syncthreads();

        // ---- Reduce ksplits + bias -> raw gates ----
        if (tid < 128) {
            if (s < S_LEN) {
                #pragma unroll
                for (int i = 0; i < 4; i++) {
                    int o = tid * 4 + i;                  // o = r*16 + b
                    const float* rp = sm + OFF_RED0 + o * 6;
                    float v = sm[OFF_BIAS + (o >> 4)];
                    v += rp[0] + rp[1] + rp[2] + rp[3] + rp[4] + rp[5];
                    sm[OFF_GATE + o] = v;
                }
            }
        } else {
            if (s >= 1) {
                #pragma unroll
                for (int i = 0; i < 4; i++) {
                    int o = (tid - 128) * 4 + i;
                    const float* rp = sm + OFF_RED1 + o * 10;
                    float v = sm[OFF_BIAS + 32 + (o >> 4)];
                    v += rp[0] + rp[1] + rp[2] + rp[3] + rp[4];
                    v += rp[5] + rp[6] + rp[7] + rp[8] + rp[9];
                    sm[OFF_GATE + 512 + o] = v;
                }
            }
        }
        __syncthreads();

        // ---- Gate nonlinearities + cell update + publish ----
        {
            bool act = up_layer ? (s >= 1) : (s < S_LEN);
            if (act) {
                const float* G = sm + OFF_GATE + up_layer * 512;
                float gi = G[(up_u)      * 16 + up_b];
                float gf = G[(8 + up_u)  * 16 + up_b];
                float gg = G[(16 + up_u) * 16 + up_b];
                float go = G[(24 + up_u) * 16 + up_b];
                float iv = 1.f / (1.f + __expf(-gi));
                float fv = 1.f / (1.f + __expf(-gf));
                float gv = tanhf(gg);
                float ov = 1.f / (1.f + __expf(-go));
                cst = fv * cst + iv * gv;
                float h = ov * tanhf(cst);
                int bglob = bg * 16 + up_b;
                if (up_layer == 0) {
                    g_h0buf[s & 1][bglob * HID + slice * 8 + up_u] = h;
                } else {
                    int tt = s - 1;
                    g_h1buf[tt & 1][bglob * HID + slice * 8 + up_u] = h;
                    float pd = h * sm[OFF_WOUT + up_u];
                    pd += __shfl_down_sync(0xffffffffu, pd, 4, 8);
                    pd += __shfl_down_sync(0xffffffffu, pd, 2, 8);
                    pd += __shfl_down_sync(0xffffffffu, pd, 1, 8);
                    if (up_u == 0)
                        g_pdot[((size_t)tt * BATCH + bglob) * NSL + slice] = pd;
                }
            }
        }

        // ---- One release/acquire barrier across the 32 blocks of this batch group ----
        __threadfence();
        __syncthreads();
        if (tid == 0) {
            atomicAdd(&g_ctr[bg], 1u);
            unsigned target = 32u * (unsigned)(s + 1);
            while (*(volatile unsigned*)&g_ctr[bg] < target) { }
            __threadfence();
        }
        __syncthreads();
    }
}

// ---------------- Epilogue: reduce partial dots -> output [B,S] ----------------
__global__ void out_kernel(const float* __restrict__ b_out, float* __restrict__ out)
{
    int idx = blockIdx.x * blockDim.x + threadIdx.x;  // 0 .. B*S-1, idx = b*2048 + t
    int b = idx >> 11, t = idx & 2047;
    const float* p = g_pdot + ((size_t)t * BATCH + b) * NSL;
    float s = b_out[0];
    #pragma unroll
    for (int j = 0; j < NSL; j++) s += p[j];
    out[idx] = s;
}

// ---------------- Launch ----------------
extern "C" void kernel_launch(void* const* d_in, const int* in_sizes, int n_in,
                              void* d_out, int out_size)
{
    const float* in_states = (const float*)d_in[0];
    const float* W_in  = (const float*)d_in[1];
    const float* b_in  = (const float*)d_in[2];
    const float* W_ih0 = (const float*)d_in[3];
    const float* W_hh0 = (const float*)d_in[4];
    const float* b_ih0 = (const float*)d_in[5];
    const float* b_hh0 = (const float*)d_in[6];
    const float* W_ih1 = (const float*)d_in[7];
    const float* W_hh1 = (const float*)d_in[8];
    const float* b_ih1 = (const float*)d_in[9];
    const float* b_hh1 = (const float*)d_in[10];
    const float* W_out = (const float*)d_in[11];
    const float* b_out = (const float*)d_in[12];
    float* out = (float*)d_out;

    cudaFuncSetAttribute(lstm_persist,
                         cudaFuncAttributeMaxDynamicSharedMemorySize, SMEM_BYTES);

    fold_kernel<<<1024, 64>>>(W_ih0, W_in, b_in, b_ih0, b_hh0, b_ih1, b_hh1);
    init_kernel<<<128, 256>>>();
    lstm_persist<<<NBLK, TPB, SMEM_BYTES>>>(in_states, W_hh0, W_ih1, W_hh1, W_out);
    out_kernel<<<512, 256>>>(b_out, out);
}

// round 4
// speedup vs baseline: 1.0500x; 1.0500x over previous
#include <cuda_runtime.h>
#include <math.h>

// ---------------- Problem constants ----------------
#define S_LEN 2048
#define BATCH 64
#define FEAT  40
#define EMBD  128
#define HID   256

// Partition: 4 batch-groups x 32 hidden-slices = 128 persistent blocks
#define NBG  4
#define NSL  32
#define NBLK 128
#define TPB  256

// Padded K strides (floats). 44 % 32 == 268 % 32 == 12 -> u*stride covers 8
// distinct bank groups (0,12,24,4,16,28,8,20) => conflict-free weight LDS.
#define XS   44      // x-part row stride (>= 40)
#define HS   268     // h-part row stride (>= 256)

// SMEM layout (float offsets)
#define OFF_W0X  0                         // [32][44]  layer0 x-weights (folded)
#define OFF_W0H  (OFF_W0X + 32*XS)         // [32][268] layer0 h-weights (W_hh0)
#define OFF_W1A  (OFF_W0H + 32*HS)         // [32][268] layer1 h0-weights (W_ih1)
#define OFF_W1B  (OFF_W1A + 32*HS)         // [32][268] layer1 h1-weights (W_hh1)
#define OFF_XB   (OFF_W1B + 32*HS)         // [2][16][44] double-buffered x
#define OFF_H0B  (OFF_XB + 2*16*XS)        // [16][268] h0[s-1]
#define OFF_H1B  (OFF_H0B + 16*HS)         // [16][268] h1[s-2]
#define SMEM_FLOATS (OFF_H1B + 16*HS)
#define SMEM_BYTES  (SMEM_FLOATS * 4)      // ~148.5 KB

// ---------------- Device scratch (static, no runtime alloc) ----------------
__device__ float    g_Wfold[1024 * FEAT];          // W_ih0 @ W_in  [1024,40]
__device__ float    g_bias0[1024];                 // W_ih0@b_in + b_ih0 + b_hh0
__device__ float    g_bias1[1024];                 // b_ih1 + b_hh1
__device__ float    g_h0buf[2][BATCH * HID];       // double-buffered h0 (time parity)
__device__ float    g_h1buf[2][BATCH * HID];       // double-buffered h1 (time parity)
__device__ unsigned g_ctr[NBG];                    // per batch-group arrival counters
__device__ float    g_pdot[(size_t)S_LEN * BATCH * NSL];  // partial output dots

// ---------------- Fast activations ----------------
__device__ __forceinline__ float sig_(float x)  { return 1.f / (1.f + __expf(-x)); }
__device__ __forceinline__ float tanh_(float x) { return __fdividef(2.f, 1.f + __expf(-2.f * x)) - 1.f; }

// ---------------- Prologue: fold input projection into layer0 ----------------
__global__ void fold_kernel(const float* __restrict__ W_ih0,
                            const float* __restrict__ W_in,
                            const float* __restrict__ b_in,
                            const float* __restrict__ b_ih0,
                            const float* __restrict__ b_hh0,
                            const float* __restrict__ b_ih1,
                            const float* __restrict__ b_hh1)
{
    int r = blockIdx.x;          // 0..1023 gate row
    int t = threadIdx.x;         // 0..63
    if (t < FEAT) {
        float s = 0.f;
        for (int e = 0; e < EMBD; e++)
            s += W_ih0[r * EMBD + e] * W_in[e * FEAT + t];
        g_Wfold[r * FEAT + t] = s;
    } else if (t == 63) {
        float s = b_ih0[r] + b_hh0[r];
        for (int e = 0; e < EMBD; e++)
            s += W_ih0[r * EMBD + e] * b_in[e];
        g_bias0[r] = s;
        g_bias1[r] = b_ih1[r] + b_hh1[r];
    }
}

// ---------------- Prologue: zero state buffers + barrier counters ----------------
__global__ void init_kernel()
{
    int i = blockIdx.x * blockDim.x + threadIdx.x;   // 0..32767
    ((float*)g_h0buf)[i] = 0.f;
    ((float*)g_h1buf)[i] = 0.f;
    if (i < NBG) g_ctr[i] = 0u;
}

// ---------------- GEMM fragment: 4 gate-dots for one (u,b) cell ----------------
// wrow points at weight row for gate 0 of this thread's unit (row stride RS floats,
// gates at +8*RS); inrow at this thread's batch input row. NIT float4 iterations.
template<int NIT, int RS>
__device__ __forceinline__ void gpart(const float* wrow, const float* inrow,
                                      float& a0, float& a1, float& a2, float& a3)
{
    const float4* hp = (const float4*)inrow;
    const float4* w0 = (const float4*)(wrow);
    const float4* w1 = (const float4*)(wrow + 8 * RS);
    const float4* w2 = (const float4*)(wrow + 16 * RS);
    const float4* w3 = (const float4*)(wrow + 24 * RS);
    #pragma unroll 8
    for (int k = 0; k < NIT; k++) {
        float4 h = hp[k];
        float4 x0 = w0[k];
        a0 += x0.x * h.x; a0 += x0.y * h.y; a0 += x0.z * h.z; a0 += x0.w * h.w;
        float4 x1 = w1[k];
        a1 += x1.x * h.x; a1 += x1.y * h.y; a1 += x1.z * h.z; a1 += x1.w * h.w;
        float4 x2 = w2[k];
        a2 += x2.x * h.x; a2 += x2.y * h.y; a2 += x2.z * h.z; a2 += x2.w * h.w;
        float4 x3 = w3[k];
        a3 += x3.x * h.x; a3 += x3.y * h.y; a3 += x3.z * h.z; a3 += x3.w * h.w;
    }
}

// ---------------- Persistent wavefront recurrence kernel ----------------
__global__ void __launch_bounds__(TPB, 1)
lstm_persist(const float* __restrict__ in_states,
             const float* __restrict__ W_hh0,
             const float* __restrict__ W_ih1,
             const float* __restrict__ W_hh1,
             const float* __restrict__ W_out)
{
    extern __shared__ float sm[];
    const int tid   = threadIdx.x;
    const int lane  = tid & 31;
    const int wid   = tid >> 5;
    const int slice = blockIdx.x & 31;   // owns hidden units slice*8 .. slice*8+7
    const int bg    = blockIdx.x >> 5;   // batches bg*16 .. bg*16+15

    // ---- Load weights into SMEM ----
    for (int i = tid; i < 32 * FEAT; i += TPB) {       // W0X: folded x weights
        int r = i / FEAT, k = i - r * FEAT;
        int grow = (r >> 3) * 256 + slice * 8 + (r & 7);
        sm[OFF_W0X + r * XS + k] = g_Wfold[grow * FEAT + k];
    }
    for (int i = tid; i < 32 * HID; i += TPB) {        // W0H / W1A / W1B
        int r = i >> 8, k = i & 255;
        int grow = (r >> 3) * 256 + slice * 8 + (r & 7);
        sm[OFF_W0H + r * HS + k] = W_hh0[grow * HID + k];
        sm[OFF_W1A + r * HS + k] = W_ih1[grow * HID + k];
        sm[OFF_W1B + r * HS + k] = W_hh1[grow * HID + k];
    }

    // ---- Per-thread role: one (layer, batch, unit) cell ----
    const int layer = wid >> 2;              // warps 0-3: layer0, 4-7: layer1
    const int u     = lane & 7;
    const int bl    = (wid & 3) * 4 + (lane >> 3);     // 0..15
    const int bglob = bg * 16 + bl;

    float bias[4], wout = 0.f;
    {
        const float* bsrc = layer ? g_bias1 : g_bias0;
        #pragma unroll
        for (int g = 0; g < 4; g++) bias[g] = bsrc[g * 256 + slice * 8 + u];
        if (layer) wout = W_out[slice * 8 + u];
    }
    float cst = 0.f;

    // ---- Stage x[0] into XB[0] ----
    for (int i = tid; i < 16 * FEAT; i += TPB) {
        int b = i / FEAT, f = i - b * FEAT;
        sm[OFF_XB + b * XS + f] =
            in_states[(size_t)(bg * 16 + b) * (S_LEN * FEAT) + f];
    }
    __syncthreads();

    // ---- Wavefront: step s computes h0[s] (layer0) and h1[s-1] (layer1) ----
    for (int s = 0; s <= S_LEN; s++) {

        // ---- Stage h0[s-1], h1[s-2] into SMEM (single copy of h0) ----
        {
            const float4* h0p = (const float4*)(g_h0buf[(s + 1) & 1] + bg * 16 * HID);
            const float4* h1p = (const float4*)(g_h1buf[s & 1]       + bg * 16 * HID);
            #pragma unroll
            for (int it = 0; it < 4; it++) {
                int i = tid + it * TPB;            // 0..1023
                int b = i >> 6, k4 = i & 63;
                *(float4*)&sm[OFF_H0B + b * HS + k4 * 4] = h0p[b * 64 + k4];
                *(float4*)&sm[OFF_H1B + b * HS + k4 * 4] = h1p[b * 64 + k4];
            }
        }
        __syncthreads();

        // ---- GEMM (full-K per thread) + activation + publish ----
        if (layer == 0) {
            if (s < S_LEN) {
                float a0 = bias[0], a1 = bias[1], a2 = bias[2], a3 = bias[3];
                gpart<10, XS>(sm + OFF_W0X + u * XS,
                              sm + OFF_XB + (s & 1) * 16 * XS + bl * XS,
                              a0, a1, a2, a3);
                gpart<64, HS>(sm + OFF_W0H + u * HS,
                              sm + OFF_H0B + bl * HS,
                              a0, a1, a2, a3);
                float iv = sig_(a0), fv = sig_(a1), gv = tanh_(a2), ov = sig_(a3);
                cst = fv * cst + iv * gv;
                float h = ov * tanh_(cst);
                g_h0buf[s & 1][bglob * HID + slice * 8 + u] = h;
            }
        } else {
            if (s >= 1) {
                float a0 = bias[0], a1 = bias[1], a2 = bias[2], a3 = bias[3];
                gpart<64, HS>(sm + OFF_W1A + u * HS,
                              sm + OFF_H0B + bl * HS,
                              a0, a1, a2, a3);
                gpart<64, HS>(sm + OFF_W1B + u * HS,
                              sm + OFF_H1B + bl * HS,
                              a0, a1, a2, a3);
                float iv = sig_(a0), fv = sig_(a1), gv = tanh_(a2), ov = sig_(a3);
                cst = fv * cst + iv * gv;
                float h = ov * tanh_(cst);
                int tt = s - 1;
                g_h1buf[tt & 1][bglob * HID + slice * 8 + u] = h;
                float pd = h * wout;
                pd += __shfl_down_sync(0xffffffffu, pd, 4, 8);
                pd += __shfl_down_sync(0xffffffffu, pd, 2, 8);
                pd += __shfl_down_sync(0xffffffffu, pd, 1, 8);
                if (u == 0)
                    g_pdot[((size_t)tt * BATCH + bglob) * NSL + slice] = pd;
            }
        }

        if (s == S_LEN) break;

        // ---- Release/acquire barrier across the 32 blocks of this batch group;
        //      warps 1-7 stage x[s+1] under the spin ----
        __threadfence();
        __syncthreads();
        if (tid == 0) {
            atomicAdd(&g_ctr[bg], 1u);
            unsigned target = 32u * (unsigned)(s + 1);
            while (*(volatile unsigned*)&g_ctr[bg] < target) { }
            __threadfence();
        } else if (wid > 0) {
            if (s + 1 < S_LEN) {
                int xoff = OFF_XB + ((s + 1) & 1) * 16 * XS;
                for (int i = tid - 32; i < 16 * FEAT; i += TPB - 32) {
                    int b = i / FEAT, f = i - b * FEAT;
                    sm[xoff + b * XS + f] =
                        in_states[((size_t)(bg * 16 + b) * S_LEN + (s + 1)) * FEAT + f];
                }
            }
        }
        __syncthreads();
    }
}

// ---------------- Epilogue: reduce partial dots -> output [B,S] ----------------
__global__ void out_kernel(const float* __restrict__ b_out, float* __restrict__ out)
{
    int idx = blockIdx.x * blockDim.x + threadIdx.x;  // idx = b*2048 + t
    int b = idx >> 11, t = idx & 2047;
    const float* p = g_pdot + ((size_t)t * BATCH + b) * NSL;
    float s = b_out[0];
    #pragma unroll
    for (int j = 0; j < NSL; j++) s += p[j];
    out[idx] = s;
}

// ---------------- Launch ----------------
extern "C" void kernel_launch(void* const* d_in, const int* in_sizes, int n_in,
                              void* d_out, int out_size)
{
    const float* in_states = (const float*)d_in[0];
    const float* W_in  = (const float*)d_in[1];
    const float* b_in  = (const float*)d_in[2];
    const float* W_ih0 = (const float*)d_in[3];
    const float* W_hh0 = (const float*)d_in[4];
    const float* b_ih0 = (const float*)d_in[5];
    const float* b_hh0 = (const float*)d_in[6];
    const float* W_ih1 = (const float*)d_in[7];
    const float* W_hh1 = (const float*)d_in[8];
    const float* b_ih1 = (const float*)d_in[9];
    const float* b_hh1 = (const float*)d_in[10];
    const float* W_out = (const float*)d_in[11];
    const float* b_out = (const float*)d_in[12];
    float* out = (float*)d_out;

    cudaFuncSetAttribute(lstm_persist,
                         cudaFuncAttributeMaxDynamicSharedMemorySize, SMEM_BYTES);

    fold_kernel<<<1024, 64>>>(W_ih0, W_in, b_in, b_ih0, b_hh0, b_ih1, b_hh1);
    init_kernel<<<128, 256>>>();
    lstm_persist<<<NBLK, TPB, SMEM_BYTES>>>(in_states, W_hh0, W_ih1, W_hh1, W_out);
    out_kernel<<<512, 256>>>(b_out, out);
}

// round 5
// speedup vs baseline: 1.1085x; 1.0557x over previous
#include <cuda_runtime.h>
#include <math.h>

// ---------------- Problem constants ----------------
#define S_LEN 2048
#define BATCH 64
#define FEAT  40
#define EMBD  128
#define HID   256

// Partition: 4 batch-groups x 32 hidden-slices = 128 persistent blocks
#define NBG  4
#define NSL  32
#define NBLK 128
#define TPB  256

// Padded K strides (floats). 44 % 32 == 268 % 32 == 12 -> u*stride covers 8
// distinct bank groups => conflict-free weight LDS; 4 h-rows also distinct.
#define XS   44      // x row stride (>= 40), 176B (16B multiple)
#define HS   268     // h row stride (>= 256), 1072B (16B multiple)

// SMEM layout (float offsets)
#define OFF_W0X  0                         // [32][44]  layer0 x-weights (folded)
#define OFF_W0H  (OFF_W0X + 32*XS)         // [32][268] layer0 h-weights (W_hh0)
#define OFF_W1A  (OFF_W0H + 32*HS)         // [32][268] layer1 h0-weights (W_ih1)
#define OFF_W1B  (OFF_W1A + 32*HS)         // [32][268] layer1 h1-weights (W_hh1)
#define OFF_XB   (OFF_W1B + 32*HS)         // [16][44]  x[s]
#define OFF_H0B  (OFF_XB + 16*XS)          // [16][268] h0[s-1]
#define OFF_H1B  (OFF_H0B + 16*HS)         // [16][268] h1[s-2]
#define OFF_MBAR (OFF_H1B + 16*HS)         // mbarrier (8B)
#define SMEM_FLOATS (OFF_MBAR + 2)
#define SMEM_BYTES  (SMEM_FLOATS * 4)      // ~145.7 KB

// ---------------- Device scratch (static, no runtime alloc) ----------------
__device__ float    g_Wfold[1024 * FEAT];
__device__ float    g_bias0[1024];
__device__ float    g_bias1[1024];
__device__ float    g_h0buf[2][BATCH * HID];
__device__ float    g_h1buf[2][BATCH * HID];
__device__ unsigned g_ctr[NBG];
__device__ float    g_pdot[(size_t)S_LEN * BATCH * NSL];

// ---------------- Fast activations ----------------
__device__ __forceinline__ float sig_(float x)  { return 1.f / (1.f + __expf(-x)); }
__device__ __forceinline__ float tanh_(float x) { return __fdividef(2.f, 1.f + __expf(-2.f * x)) - 1.f; }

// ---------------- Packed f32x2 helpers ----------------
__device__ __forceinline__ void fma2(unsigned long long& acc,
                                     unsigned long long a, unsigned long long b)
{
    asm("fma.rn.f32x2 %0, %1, %2, %0;" : "+l"(acc) : "l"(a), "l"(b));
}
__device__ __forceinline__ unsigned long long pack2(float lo, float hi)
{
    unsigned long long r;
    asm("mov.b64 %0, {%1, %2};" : "=l"(r) : "f"(lo), "f"(hi));
    return r;
}
__device__ __forceinline__ float hsum2(unsigned long long p)
{
    float lo, hi;
    asm("mov.b64 {%0, %1}, %2;" : "=f"(lo), "=f"(hi) : "l"(p));
    return lo + hi;
}

// ---------------- Prologue kernels ----------------
__global__ void fold_kernel(const float* __restrict__ W_ih0,
                            const float* __restrict__ W_in,
                            const float* __restrict__ b_in,
                            const float* __restrict__ b_ih0,
                            const float* __restrict__ b_hh0,
                            const float* __restrict__ b_ih1,
                            const float* __restrict__ b_hh1)
{
    int r = blockIdx.x;          // 0..1023 gate row
    int t = threadIdx.x;         // 0..63
    if (t < FEAT) {
        float s = 0.f;
        for (int e = 0; e < EMBD; e++)
            s += W_ih0[r * EMBD + e] * W_in[e * FEAT + t];
        g_Wfold[r * FEAT + t] = s;
    } else if (t == 63) {
        float s = b_ih0[r] + b_hh0[r];
        for (int e = 0; e < EMBD; e++)
            s += W_ih0[r * EMBD + e] * b_in[e];
        g_bias0[r] = s;
        g_bias1[r] = b_ih1[r] + b_hh1[r];
    }
}

__global__ void init_kernel()
{
    int i = blockIdx.x * blockDim.x + threadIdx.x;
    ((float*)g_h0buf)[i] = 0.f;
    ((float*)g_h1buf)[i] = 0.f;
    if (i < NBG) g_ctr[i] = 0u;
}

// ---------------- Packed GEMM fragment: 4 gate-dots for one (u,b) cell ----------------
template<int NIT, int RS>
__device__ __forceinline__ void gpart2(const float* wrow, const float* inrow,
                                       unsigned long long& p0, unsigned long long& p1,
                                       unsigned long long& p2, unsigned long long& p3)
{
    const ulonglong2* hp = (const ulonglong2*)inrow;
    const ulonglong2* w0 = (const ulonglong2*)(wrow);
    const ulonglong2* w1 = (const ulonglong2*)(wrow + 8 * RS);
    const ulonglong2* w2 = (const ulonglong2*)(wrow + 16 * RS);
    const ulonglong2* w3 = (const ulonglong2*)(wrow + 24 * RS);
    #pragma unroll 8
    for (int k = 0; k < NIT; k++) {
        ulonglong2 h = hp[k];
        ulonglong2 a0 = w0[k];
        fma2(p0, a0.x, h.x); fma2(p0, a0.y, h.y);
        ulonglong2 a1 = w1[k];
        fma2(p1, a1.x, h.x); fma2(p1, a1.y, h.y);
        ulonglong2 a2 = w2[k];
        fma2(p2, a2.x, h.x); fma2(p2, a2.y, h.y);
        ulonglong2 a3 = w3[k];
        fma2(p3, a3.x, h.x); fma2(p3, a3.y, h.y);
    }
}

// ---------------- TMA 1D bulk copy ----------------
__device__ __forceinline__ void bulk_g2s(unsigned dst_smem, const void* src,
                                         unsigned bytes, unsigned mbar)
{
    asm volatile(
        "cp.async.bulk.shared::cluster.global.mbarrier::complete_tx::bytes "
        "[%0], [%1], %2, [%3];"
        :: "r"(dst_smem), "l"(src), "r"(bytes), "r"(mbar) : "memory");
}

// ---------------- Persistent wavefront recurrence kernel ----------------
__global__ void __launch_bounds__(TPB, 1)
lstm_persist(const float* __restrict__ in_states,
             const float* __restrict__ W_hh0,
             const float* __restrict__ W_ih1,
             const float* __restrict__ W_hh1,
             const float* __restrict__ W_out)
{
    extern __shared__ float sm[];
    const int tid   = threadIdx.x;
    const int lane  = tid & 31;
    const int wid   = tid >> 5;
    const int slice = blockIdx.x & 31;   // hidden units slice*8 .. slice*8+7
    const int bg    = blockIdx.x >> 5;   // batches bg*16 .. bg*16+15

    unsigned smem_base;
    asm("{ .reg .u64 t; cvta.to.shared.u64 t, %1; cvt.u32.u64 %0, t; }"
        : "=r"(smem_base) : "l"(sm));
    const unsigned mbar = smem_base + OFF_MBAR * 4;

    // ---- mbarrier init: 8 arrivals (one per warp leader) per phase ----
    if (tid == 0) {
        asm volatile("mbarrier.init.shared.b64 [%0], %1;" :: "r"(mbar), "r"(8u) : "memory");
    }

    // ---- Load weights into SMEM ----
    for (int i = tid; i < 32 * FEAT; i += TPB) {
        int r = i / FEAT, k = i - r * FEAT;
        int grow = (r >> 3) * 256 + slice * 8 + (r & 7);
        sm[OFF_W0X + r * XS + k] = g_Wfold[grow * FEAT + k];
    }
    for (int i = tid; i < 32 * HID; i += TPB) {
        int r = i >> 8, k = i & 255;
        int grow = (r >> 3) * 256 + slice * 8 + (r & 7);
        sm[OFF_W0H + r * HS + k] = W_hh0[grow * HID + k];
        sm[OFF_W1A + r * HS + k] = W_ih1[grow * HID + k];
        sm[OFF_W1B + r * HS + k] = W_hh1[grow * HID + k];
    }

    // ---- Per-thread role: one (layer, batch, unit) cell ----
    const int layer = wid >> 2;                        // warps 0-3: L0, 4-7: L1
    const int u     = lane & 7;
    const int bl    = (wid & 3) * 4 + (lane >> 3);     // 0..15
    const int bglob = bg * 16 + bl;

    float bias[4], wout = 0.f;
    {
        const float* bsrc = layer ? g_bias1 : g_bias0;
        #pragma unroll
        for (int g = 0; g < 4; g++) bias[g] = bsrc[g * 256 + slice * 8 + u];
        if (layer) wout = W_out[slice * 8 + u];
    }
    float cst = 0.f;
    __syncthreads();

    // ---- Wavefront: step s computes h0[s] (layer0) and h1[s-1] (layer1) ----
    for (int s = 0; s <= S_LEN; s++) {

        // 1. Wait for all 32 blocks of this batch group to have finished step s-1
        if (s > 0) {
            if (tid == 0) {
                unsigned target = 32u * (unsigned)s;
                unsigned v;
                do {
                    asm volatile("ld.acquire.gpu.global.u32 %0, [%1];"
                                 : "=r"(v) : "l"(&g_ctr[bg]) : "memory");
                } while (v < target);
            }
            __syncthreads();
        }

        // 2. Warp leaders issue TMA bulk copies for h0[s-1], h1[s-2], x[s]
        if (lane == 0) {
            unsigned bytes = (s < S_LEN) ? (2u * 1024u * 2u + 2u * 160u)
                                         : (2u * 1024u * 2u);
            asm volatile("mbarrier.arrive.expect_tx.shared.b64 _, [%0], %1;"
                         :: "r"(mbar), "r"(bytes) : "memory");
            const float* h0src = g_h0buf[(s + 1) & 1] + (size_t)bg * 16 * HID;
            const float* h1src = g_h1buf[s & 1]       + (size_t)bg * 16 * HID;
            #pragma unroll
            for (int j = 0; j < 2; j++) {
                int b = wid * 2 + j;
                bulk_g2s(smem_base + (OFF_H0B + b * HS) * 4, h0src + b * HID, 1024u, mbar);
                bulk_g2s(smem_base + (OFF_H1B + b * HS) * 4, h1src + b * HID, 1024u, mbar);
                if (s < S_LEN)
                    bulk_g2s(smem_base + (OFF_XB + b * XS) * 4,
                             in_states + ((size_t)(bg * 16 + b) * S_LEN + s) * FEAT,
                             160u, mbar);
            }
        }

        // 3. Wait for copies (phase parity = s&1)
        {
            unsigned phase = (unsigned)(s & 1);
            unsigned done;
            asm volatile(
                "{\n\t.reg .pred p;\n\t"
                "mbarrier.try_wait.parity.acquire.cta.shared::cta.b64 p, [%1], %2;\n\t"
                "selp.b32 %0, 1, 0, p;\n\t}"
                : "=r"(done) : "r"(mbar), "r"(phase) : "memory");
            if (!done) {
                asm volatile(
                    "{\n\t.reg .pred P1;\n\t"
                    "WL_%=:\n\t"
                    "mbarrier.try_wait.parity.acquire.cta.shared::cta.b64 P1, [%0], %1, 0x989680;\n\t"
                    "@P1 bra.uni WD_%=;\n\t"
                    "bra.uni WL_%=;\n\t"
                    "WD_%=:\n\t}"
                    :: "r"(mbar), "r"(phase) : "memory");
            }
        }

        // 4. GEMM (full-K, packed f32x2) + activation + publish
        if (layer == 0) {
            if (s < S_LEN) {
                unsigned long long p0 = pack2(bias[0], 0.f), p1 = pack2(bias[1], 0.f);
                unsigned long long p2 = pack2(bias[2], 0.f), p3 = pack2(bias[3], 0.f);
                gpart2<10, XS>(sm + OFF_W0X + u * XS, sm + OFF_XB + bl * XS, p0, p1, p2, p3);
                gpart2<64, HS>(sm + OFF_W0H + u * HS, sm + OFF_H0B + bl * HS, p0, p1, p2, p3);
                float iv = sig_(hsum2(p0)), fv = sig_(hsum2(p1));
                float gv = tanh_(hsum2(p2)), ov = sig_(hsum2(p3));
                cst = fv * cst + iv * gv;
                float h = ov * tanh_(cst);
                __stcg(&g_h0buf[s & 1][bglob * HID + slice * 8 + u], h);
            }
        } else {
            if (s >= 1) {
                unsigned long long p0 = pack2(bias[0], 0.f), p1 = pack2(bias[1], 0.f);
                unsigned long long p2 = pack2(bias[2], 0.f), p3 = pack2(bias[3], 0.f);
                gpart2<64, HS>(sm + OFF_W1A + u * HS, sm + OFF_H0B + bl * HS, p0, p1, p2, p3);
                gpart2<64, HS>(sm + OFF_W1B + u * HS, sm + OFF_H1B + bl * HS, p0, p1, p2, p3);
                float iv = sig_(hsum2(p0)), fv = sig_(hsum2(p1));
                float gv = tanh_(hsum2(p2)), ov = sig_(hsum2(p3));
                cst = fv * cst + iv * gv;
                float h = ov * tanh_(cst);
                int tt = s - 1;
                __stcg(&g_h1buf[tt & 1][bglob * HID + slice * 8 + u], h);
                float pd = h * wout;
                pd += __shfl_down_sync(0xffffffffu, pd, 4, 8);
                pd += __shfl_down_sync(0xffffffffu, pd, 2, 8);
                pd += __shfl_down_sync(0xffffffffu, pd, 1, 8);
                if (u == 0)
                    __stcg(&g_pdot[((size_t)tt * BATCH + bglob) * NSL + slice], pd);
            }
        }

        if (s == S_LEN) break;

        // 5./6. Ensure all stores done, then release-arrive on the group counter
        __syncthreads();
        if (tid == 0) {
            asm volatile("red.release.gpu.global.add.u32 [%0], %1;"
                         :: "l"(&g_ctr[bg]), "r"(1u) : "memory");
        }
    }
}

// ---------------- Epilogue: reduce partial dots -> output [B,S] ----------------
__global__ void out_kernel(const float* __restrict__ b_out, float* __restrict__ out)
{
    int idx = blockIdx.x * blockDim.x + threadIdx.x;  // idx = b*2048 + t
    int b = idx >> 11, t = idx & 2047;
    const float* p = g_pdot + ((size_t)t * BATCH + b) * NSL;
    float s = b_out[0];
    #pragma unroll
    for (int j = 0; j < NSL; j++) s += p[j];
    out[idx] = s;
}

// ---------------- Launch ----------------
extern "C" void kernel_launch(void* const* d_in, const int* in_sizes, int n_in,
                              void* d_out, int out_size)
{
    const float* in_states = (const float*)d_in[0];
    const float* W_in  = (const float*)d_in[1];
    const float* b_in  = (const float*)d_in[2];
    const float* W_ih0 = (const float*)d_in[3];
    const float* W_hh0 = (const float*)d_in[4];
    const float* b_ih0 = (const float*)d_in[5];
    const float* b_hh0 = (const float*)d_in[6];
    const float* W_ih1 = (const float*)d_in[7];
    const float* W_hh1 = (const float*)d_in[8];
    const float* b_ih1 = (const float*)d_in[9];
    const float* b_hh1 = (const float*)d_in[10];
    const float* W_out = (const float*)d_in[11];
    const float* b_out = (const float*)d_in[12];
    float* out = (float*)d_out;

    cudaFuncSetAttribute(lstm_persist,
                         cudaFuncAttributeMaxDynamicSharedMemorySize, SMEM_BYTES);

    fold_kernel<<<1024, 64>>>(W_ih0, W_in, b_in, b_ih0, b_hh0, b_ih1, b_hh1);
    init_kernel<<<128, 256>>>();
    lstm_persist<<<NBLK, TPB, SMEM_BYTES>>>(in_states, W_hh0, W_ih1, W_hh1, W_out);
    out_kernel<<<512, 256>>>(b_out, out);
}